// round 6
// baseline (speedup 1.0000x reference)
#include <cuda_runtime.h>
#include <cstdint>

#define NVOX 400000
#define NPTS 800000

// ---------------- scratch (device globals; zero-initialized at load) -------
__device__ float g_red [(size_t)NVOX * 64];        // relu(x@Wred+b)      102.4 MB
__device__ float g_rW1 [(size_t)NVOX * 64];        // red @ W_lin1[0:64]  102.4 MB
__device__ float g_ssum[(size_t)4 * NVOX * 64];    // segment sums of red 409.6 MB
__device__ float g_cnt [(size_t)4 * NVOX];         // 6.4 MB
__device__ float g_att [(size_t)4 * NVOX * 32];    // 204.8 MB
__device__ float g_proj[(size_t)NVOX * 64];        // 102.4 MB
__device__ int   g_vout[(size_t)NVOX];             // voxel -> out-row+1 (0 = absent)
__device__ float g_Wc  [32 * 64];                  // W_out @ W_lin1[64:128]

__device__ __forceinline__ float sigm(float x) { return 1.f / (1.f + __expf(-x)); }

__device__ __forceinline__ void amaxf(float* a, float v) {
    if (v >= 0.f) atomicMax((int*)a, __float_as_int(v));
    else          atomicMin((unsigned int*)a, __float_as_uint(v));
}

__device__ __forceinline__ void red4(float* p, float a, float b, float c, float d) {
    asm volatile("red.global.add.v4.f32 [%0], {%1,%2,%3,%4};"
                 :: "l"(p), "f"(a), "f"(b), "f"(c), "f"(d) : "memory");
}

// ---------------- init kernels ---------------------------------------------
__global__ void k_fill_out(float* __restrict__ out, int n) {
    int i = blockIdx.x * blockDim.x + threadIdx.x;
    if (i < n) ((unsigned int*)out)[i] = 0xFF800000u;   // -inf
}

// Wc[k][c] = sum_t W_out[k][t] * W_lin1[64+t][c]
__global__ void k_wc(const float* __restrict__ Wout, const float* __restrict__ W1) {
    int idx = blockIdx.x * blockDim.x + threadIdx.x;   // 2048 = 32*64
    if (idx >= 32 * 64) return;
    int k = idx >> 6, c = idx & 63;
    float s = 0.f;
    for (int t = 0; t < 64; t++) s += Wout[k * 64 + t] * W1[(64 + t) * 64 + c];
    g_Wc[idx] = s;
}

// ---------------- K1: red = relu(x@Wred+b); store red; scatter to 4 scales -
__global__ __launch_bounds__(128) void k_red(
    const float* __restrict__ x, const float* __restrict__ W,
    const float* __restrict__ b,
    const int* __restrict__ i0, const int* __restrict__ i1,
    const int* __restrict__ i2, const int* __restrict__ i3)
{
    __shared__ float4 sW[64 * 16];   // 16 KB  W_red
    int tid = threadIdx.x;
    for (int i = tid; i < 64 * 16; i += 128) sW[i] = ((const float4*)W)[i];
    __syncthreads();

    int v = blockIdx.x * 128 + tid;
    if (v >= NVOX) return;
    const float4* xr = (const float4*)(x + (size_t)v * 64);

    float acc[64];
#pragma unroll
    for (int c = 0; c < 64; c++) acc[c] = 0.f;

#pragma unroll
    for (int kq = 0; kq < 16; kq++) {
        float4 x4 = __ldg(xr + kq);
        float xv[4] = {x4.x, x4.y, x4.z, x4.w};
#pragma unroll
        for (int kk = 0; kk < 4; kk++) {
            int k = kq * 4 + kk;
#pragma unroll
            for (int c4 = 0; c4 < 16; c4++) {
                float4 w = sW[k * 16 + c4];
                acc[c4 * 4 + 0] += xv[kk] * w.x;
                acc[c4 * 4 + 1] += xv[kk] * w.y;
                acc[c4 * 4 + 2] += xv[kk] * w.z;
                acc[c4 * 4 + 3] += xv[kk] * w.w;
            }
        }
    }
    float red[64];
#pragma unroll
    for (int c = 0; c < 64; c++) red[c] = fmaxf(acc[c] + __ldg(b + c), 0.f);

    float4* rr = (float4*)(g_red + (size_t)v * 64);
#pragma unroll
    for (int q = 0; q < 16; q++)
        rr[q] = make_float4(red[4 * q], red[4 * q + 1], red[4 * q + 2], red[4 * q + 3]);

    const int* invs[4] = {i0, i1, i2, i3};
#pragma unroll
    for (int j = 0; j < 4; j++) {
        int s = __ldg(invs[j] + v);
        float* dst = g_ssum + ((size_t)j * NVOX + s) * 64;
#pragma unroll
        for (int q = 0; q < 16; q++)
            red4(dst + q * 4, red[4 * q], red[4 * q + 1], red[4 * q + 2], red[4 * q + 3]);
        atomicAdd(g_cnt + (size_t)j * NVOX + s, 1.0f);
    }
}

// ---------------- K1b: rW1 = red @ W1[0:64]  (2 voxels per thread) ---------
__global__ __launch_bounds__(128) void k_rw1(const float* __restrict__ W1)
{
    __shared__ float4 sW1[64 * 16];   // 16 KB  W_lin1 rows 0..63
    int tid = threadIdx.x;
    for (int i = tid; i < 64 * 16; i += 128) sW1[i] = ((const float4*)W1)[i];
    __syncthreads();

    int v0 = blockIdx.x * 256 + tid;
    if (v0 >= NVOX) return;
    int v1 = v0 + 128;
    bool has1 = v1 < NVOX;
    int v1s = has1 ? v1 : v0;

    const float4* r0 = (const float4*)(g_red + (size_t)v0 * 64);
    const float4* r1 = (const float4*)(g_red + (size_t)v1s * 64);

    float a0[64], a1[64];
#pragma unroll
    for (int c = 0; c < 64; c++) { a0[c] = 0.f; a1[c] = 0.f; }

#pragma unroll
    for (int kq = 0; kq < 16; kq++) {
        float4 x0 = __ldg(r0 + kq);
        float4 x1 = __ldg(r1 + kq);
        float xv0[4] = {x0.x, x0.y, x0.z, x0.w};
        float xv1[4] = {x1.x, x1.y, x1.z, x1.w};
#pragma unroll
        for (int kk = 0; kk < 4; kk++) {
            int k = kq * 4 + kk;
#pragma unroll
            for (int c4 = 0; c4 < 16; c4++) {
                float4 w = sW1[k * 16 + c4];
                a0[c4 * 4 + 0] += xv0[kk] * w.x; a1[c4 * 4 + 0] += xv1[kk] * w.x;
                a0[c4 * 4 + 1] += xv0[kk] * w.y; a1[c4 * 4 + 1] += xv1[kk] * w.y;
                a0[c4 * 4 + 2] += xv0[kk] * w.z; a1[c4 * 4 + 2] += xv1[kk] * w.z;
                a0[c4 * 4 + 3] += xv0[kk] * w.w; a1[c4 * 4 + 3] += xv1[kk] * w.w;
            }
        }
    }
    float4* o0 = (float4*)(g_rW1 + (size_t)v0 * 64);
#pragma unroll
    for (int q = 0; q < 16; q++)
        o0[q] = make_float4(a0[4 * q], a0[4 * q + 1], a0[4 * q + 2], a0[4 * q + 3]);
    if (has1) {
        float4* o1 = (float4*)(g_rW1 + (size_t)v1 * 64);
#pragma unroll
        for (int q = 0; q < 16; q++)
            o1[q] = make_float4(a1[4 * q], a1[4 * q + 1], a1[4 * q + 2], a1[4 * q + 3]);
    }
}

// ---------------- K2: att = relu((ssum/cnt)@W_att + b); self-clean ---------
// 4 threads per PAIR of adjacent segment rows; thread sub does cols [sub*8,+8)
__global__ __launch_bounds__(256) void k_scale(
    const float* __restrict__ Watt, const float* __restrict__ batt)
{
    __shared__ float4 sA[4 * 64 * 8];   // 32 KB all 4 scales [j][k][32]
    int tid = threadIdx.x;
    for (int i = tid; i < 4 * 64 * 8; i += 256)
        sA[i] = ((const float4*)Watt)[i];
    __syncthreads();

    long long t = (long long)blockIdx.x * 256 + tid;
    long long pair = t >> 2;
    int sub = (int)(t & 3);
    bool valid = pair < (long long)2 * NVOX;
    long long row0 = pair * 2, row1 = row0 + 1;
    float c0 = 0.f, c1 = 0.f;
    int j = 0;
    if (valid) {
        j = (int)(row0 / NVOX);
        c0 = g_cnt[row0];
        c1 = g_cnt[row1];
    }
    if (valid && (c0 != 0.f || c1 != 0.f)) {
        float ic0 = (c0 != 0.f) ? 1.f / c0 : 0.f;
        float ic1 = (c1 != 0.f) ? 1.f / c1 : 0.f;
        float4* sp0 = (float4*)(g_ssum + row0 * 64);
        float4* sp1 = (float4*)(g_ssum + row1 * 64);

        float a0[8], a1[8];
#pragma unroll
        for (int i = 0; i < 8; i++) { a0[i] = 0.f; a1[i] = 0.f; }
#pragma unroll
        for (int kq = 0; kq < 16; kq++) {
            float4 x0 = sp0[kq];
            float4 x1 = sp1[kq];
            float xv0[4] = {x0.x * ic0, x0.y * ic0, x0.z * ic0, x0.w * ic0};
            float xv1[4] = {x1.x * ic1, x1.y * ic1, x1.z * ic1, x1.w * ic1};
#pragma unroll
            for (int kk = 0; kk < 4; kk++) {
                int k = kq * 4 + kk;
                float4 w0 = sA[(j * 64 + k) * 8 + sub * 2 + 0];
                float4 w1 = sA[(j * 64 + k) * 8 + sub * 2 + 1];
                a0[0] += xv0[kk] * w0.x; a0[1] += xv0[kk] * w0.y;
                a0[2] += xv0[kk] * w0.z; a0[3] += xv0[kk] * w0.w;
                a0[4] += xv0[kk] * w1.x; a0[5] += xv0[kk] * w1.y;
                a0[6] += xv0[kk] * w1.z; a0[7] += xv0[kk] * w1.w;
                a1[0] += xv1[kk] * w0.x; a1[1] += xv1[kk] * w0.y;
                a1[2] += xv1[kk] * w0.z; a1[3] += xv1[kk] * w0.w;
                a1[4] += xv1[kk] * w1.x; a1[5] += xv1[kk] * w1.y;
                a1[6] += xv1[kk] * w1.z; a1[7] += xv1[kk] * w1.w;
            }
        }
        float bb[8];
#pragma unroll
        for (int i = 0; i < 8; i++) bb[i] = __ldg(batt + j * 32 + sub * 8 + i);
        float4 z = make_float4(0.f, 0.f, 0.f, 0.f);
        if (c0 != 0.f) {
            float4* op = (float4*)(g_att + row0 * 32) + sub * 2;
            op[0] = make_float4(fmaxf(a0[0] + bb[0], 0.f), fmaxf(a0[1] + bb[1], 0.f),
                                fmaxf(a0[2] + bb[2], 0.f), fmaxf(a0[3] + bb[3], 0.f));
            op[1] = make_float4(fmaxf(a0[4] + bb[4], 0.f), fmaxf(a0[5] + bb[5], 0.f),
                                fmaxf(a0[6] + bb[6], 0.f), fmaxf(a0[7] + bb[7], 0.f));
#pragma unroll
            for (int q = 0; q < 4; q++) sp0[sub * 4 + q] = z;
        }
        if (c1 != 0.f) {
            float4* op = (float4*)(g_att + row1 * 32) + sub * 2;
            op[0] = make_float4(fmaxf(a1[0] + bb[0], 0.f), fmaxf(a1[1] + bb[1], 0.f),
                                fmaxf(a1[2] + bb[2], 0.f), fmaxf(a1[3] + bb[3], 0.f));
            op[1] = make_float4(fmaxf(a1[4] + bb[4], 0.f), fmaxf(a1[5] + bb[5], 0.f),
                                fmaxf(a1[6] + bb[6], 0.f), fmaxf(a1[7] + bb[7], 0.f));
#pragma unroll
            for (int q = 0; q < 4; q++) sp1[sub * 4 + q] = z;
        }
    }
    __syncwarp();                       // all 4 subs done reading cnt
    if (valid && sub == 0) {
        if (c0 != 0.f) g_cnt[row0] = 0.f;
        if (c1 != 0.f) g_cnt[row1] = 0.f;
    }
}

// ---------------- K3: fusion + attention + MLP, 2 voxels per thread --------
// dynamic smem layout (floats):
//   [0,4096)      Wfcs (4*32*32)
//   [4096,6144)   Wc
//   [6144,10240)  W2
//   [10240,11264) Wfc
//   [11264,27648) sh   h staging [64][256]
//   [27648,27776) bfcs
//   [27776,27840) b2
#define FUSE_SMEM_FLOATS 27840
__global__ __launch_bounds__(128) void k_fuse(
    const float* __restrict__ Wfc,  const float* __restrict__ Wfcs,
    const float* __restrict__ bfcs, const float* __restrict__ b2,
    const float* __restrict__ W2,
    const int* __restrict__ i0, const int* __restrict__ i1,
    const int* __restrict__ i2, const int* __restrict__ i3)
{
    extern __shared__ float sm[];
    float4* sWfcs = (float4*)sm;              // 1024 float4
    float4* sWc   = (float4*)(sm + 4096);     // 512
    float4* sW2   = (float4*)(sm + 6144);     // 1024
    float4* sWfc  = (float4*)(sm + 10240);    // 256
    float*  sh    = sm + 11264;               // [64][256]
    float*  sbfcs = sm + 27648;
    float*  sb2   = sm + 27776;

    int tid = threadIdx.x;
    for (int i = tid; i < 1024; i += 128) sWfcs[i] = ((const float4*)Wfcs)[i];
    for (int i = tid; i < 512;  i += 128) sWc[i]   = ((const float4*)g_Wc)[i];
    for (int i = tid; i < 1024; i += 128) sW2[i]   = ((const float4*)W2)[i];
    for (int i = tid; i < 256;  i += 128) sWfc[i]  = ((const float4*)Wfc)[i];
    sbfcs[tid] = bfcs[tid];
    if (tid < 64) sb2[tid] = b2[tid];
    __syncthreads();

    int v0 = blockIdx.x * 256 + tid;
    if (v0 >= NVOX) return;
    int v1 = v0 + 128;
    bool has1 = v1 < NVOX;
    int v1s = has1 ? v1 : v0;

    int sgA[4] = {__ldg(i0 + v0), __ldg(i1 + v0), __ldg(i2 + v0), __ldg(i3 + v0)};
    int sgB[4] = {__ldg(i0 + v1s), __ldg(i1 + v1s), __ldg(i2 + v1s), __ldg(i3 + v1s)};

    // feat_S = sum_j s_j
    float fS0[32], fS1[32];
#pragma unroll
    for (int i = 0; i < 32; i++) { fS0[i] = 0.f; fS1[i] = 0.f; }
#pragma unroll
    for (int j = 0; j < 4; j++) {
        const float4* spA = (const float4*)(g_att + ((size_t)j * NVOX + sgA[j]) * 32);
        const float4* spB = (const float4*)(g_att + ((size_t)j * NVOX + sgB[j]) * 32);
#pragma unroll
        for (int q = 0; q < 8; q++) {
            float4 sa = __ldg(spA + q);
            float4 sb = __ldg(spB + q);
            fS0[4 * q + 0] += sa.x; fS0[4 * q + 1] += sa.y;
            fS0[4 * q + 2] += sa.z; fS0[4 * q + 3] += sa.w;
            fS1[4 * q + 0] += sb.x; fS1[4 * q + 1] += sb.y;
            fS1[4 * q + 2] += sb.z; fS1[4 * q + 3] += sb.w;
        }
    }

    // feat_Z = relu(feat_S @ W_fc)
    float fZ0[32], fZ1[32];
#pragma unroll
    for (int i = 0; i < 32; i++) { fZ0[i] = 0.f; fZ1[i] = 0.f; }
#pragma unroll
    for (int k = 0; k < 32; k++) {
        float x0 = fS0[k], x1 = fS1[k];
#pragma unroll
        for (int c4 = 0; c4 < 8; c4++) {
            float4 w = sWfc[k * 8 + c4];
            fZ0[c4 * 4 + 0] += x0 * w.x; fZ0[c4 * 4 + 1] += x0 * w.y;
            fZ0[c4 * 4 + 2] += x0 * w.z; fZ0[c4 * 4 + 3] += x0 * w.w;
            fZ1[c4 * 4 + 0] += x1 * w.x; fZ1[c4 * 4 + 1] += x1 * w.y;
            fZ1[c4 * 4 + 2] += x1 * w.z; fZ1[c4 * 4 + 3] += x1 * w.w;
        }
    }
#pragma unroll
    for (int i = 0; i < 32; i++) { fZ0[i] = fmaxf(fZ0[i], 0.f); fZ1[i] = fmaxf(fZ1[i], 0.f); }

    // m = sum_j s_j * sigmoid(fZ @ W_fcs[j] + b_fcs[j])
    float m0[32], m1[32];
#pragma unroll
    for (int i = 0; i < 32; i++) { m0[i] = 0.f; m1[i] = 0.f; }
#pragma unroll
    for (int j = 0; j < 4; j++) {
        const float4* spA = (const float4*)(g_att + ((size_t)j * NVOX + sgA[j]) * 32);
        const float4* spB = (const float4*)(g_att + ((size_t)j * NVOX + sgB[j]) * 32);
#pragma unroll
        for (int c4 = 0; c4 < 8; c4++) {
            float ba0 = sbfcs[j * 32 + 4 * c4 + 0], ba1 = sbfcs[j * 32 + 4 * c4 + 1];
            float ba2 = sbfcs[j * 32 + 4 * c4 + 2], ba3 = sbfcs[j * 32 + 4 * c4 + 3];
            float a0 = ba0, a1 = ba1, a2 = ba2, a3 = ba3;
            float e0 = ba0, e1 = ba1, e2 = ba2, e3 = ba3;
#pragma unroll
            for (int k = 0; k < 32; k++) {
                float4 w = sWfcs[(j * 32 + k) * 8 + c4];
                a0 += fZ0[k] * w.x; a1 += fZ0[k] * w.y;
                a2 += fZ0[k] * w.z; a3 += fZ0[k] * w.w;
                e0 += fZ1[k] * w.x; e1 += fZ1[k] * w.y;
                e2 += fZ1[k] * w.z; e3 += fZ1[k] * w.w;
            }
            float4 sa = __ldg(spA + c4);
            float4 sb = __ldg(spB + c4);
            m0[4 * c4 + 0] += sa.x * sigm(a0);
            m0[4 * c4 + 1] += sa.y * sigm(a1);
            m0[4 * c4 + 2] += sa.z * sigm(a2);
            m0[4 * c4 + 3] += sa.w * sigm(a3);
            m1[4 * c4 + 0] += sb.x * sigm(e0);
            m1[4 * c4 + 1] += sb.y * sigm(e1);
            m1[4 * c4 + 2] += sb.z * sigm(e2);
            m1[4 * c4 + 3] += sb.w * sigm(e3);
        }
    }

    // h = relu(rW1 + m @ Wc)  -> staged into smem per-thread slots
    const float4* rpA = (const float4*)(g_rW1 + (size_t)v0 * 64);
    const float4* rpB = (const float4*)(g_rW1 + (size_t)v1s * 64);
#pragma unroll
    for (int half = 0; half < 2; half++) {
        float a0[32], a1[32];
#pragma unroll
        for (int q = 0; q < 8; q++) {
            float4 ra = __ldg(rpA + half * 8 + q);
            float4 rb = __ldg(rpB + half * 8 + q);
            a0[4 * q + 0] = ra.x; a0[4 * q + 1] = ra.y;
            a0[4 * q + 2] = ra.z; a0[4 * q + 3] = ra.w;
            a1[4 * q + 0] = rb.x; a1[4 * q + 1] = rb.y;
            a1[4 * q + 2] = rb.z; a1[4 * q + 3] = rb.w;
        }
#pragma unroll
        for (int k = 0; k < 32; k++) {
            float x0 = m0[k], x1 = m1[k];
#pragma unroll
            for (int c4 = 0; c4 < 8; c4++) {
                float4 w = sWc[k * 16 + half * 8 + c4];
                a0[c4 * 4 + 0] += x0 * w.x; a0[c4 * 4 + 1] += x0 * w.y;
                a0[c4 * 4 + 2] += x0 * w.z; a0[c4 * 4 + 3] += x0 * w.w;
                a1[c4 * 4 + 0] += x1 * w.x; a1[c4 * 4 + 1] += x1 * w.y;
                a1[c4 * 4 + 2] += x1 * w.z; a1[c4 * 4 + 3] += x1 * w.w;
            }
        }
#pragma unroll
        for (int c = 0; c < 32; c++) {
            sh[(half * 32 + c) * 256 + tid]       = fmaxf(a0[c], 0.f);
            sh[(half * 32 + c) * 256 + tid + 128] = fmaxf(a1[c], 0.f);
        }
    }

    // proj = h @ W2 + b2  (h read back from own smem slots)
    float4* prA = (float4*)(g_proj + (size_t)v0 * 64);
    float4* prB = (float4*)(g_proj + (size_t)v1 * 64);
#pragma unroll
    for (int half = 0; half < 2; half++) {
        float p0[32], p1[32];
#pragma unroll
        for (int c = 0; c < 32; c++) { p0[c] = sb2[half * 32 + c]; p1[c] = p0[c]; }
#pragma unroll
        for (int k = 0; k < 64; k++) {
            float h0 = sh[k * 256 + tid];
            float h1 = sh[k * 256 + tid + 128];
#pragma unroll
            for (int c4 = 0; c4 < 8; c4++) {
                float4 w = sW2[k * 16 + half * 8 + c4];
                p0[c4 * 4 + 0] += h0 * w.x; p0[c4 * 4 + 1] += h0 * w.y;
                p0[c4 * 4 + 2] += h0 * w.z; p0[c4 * 4 + 3] += h0 * w.w;
                p1[c4 * 4 + 0] += h1 * w.x; p1[c4 * 4 + 1] += h1 * w.y;
                p1[c4 * 4 + 2] += h1 * w.z; p1[c4 * 4 + 3] += h1 * w.w;
            }
        }
#pragma unroll
        for (int q = 0; q < 8; q++)
            prA[half * 8 + q] = make_float4(p0[4 * q], p0[4 * q + 1],
                                            p0[4 * q + 2], p0[4 * q + 3]);
        if (has1) {
#pragma unroll
            for (int q = 0; q < 8; q++)
                prB[half * 8 + q] = make_float4(p1[4 * q], p1[4 * q + 1],
                                                p1[4 * q + 2], p1[4 * q + 3]);
        }
    }
}

// ---------------- K4a: point -> voxel out-row map (idempotent) --------------
__global__ __launch_bounds__(256) void k_map(
    const int* __restrict__ invp, const int* __restrict__ invo)
{
    int p = blockIdx.x * 256 + threadIdx.x;
    if (p >= NPTS) return;
    g_vout[__ldg(invp + p)] = __ldg(invo + p) + 1;
}

// ---------------- K4b: per present voxel, segment-max proj into out --------
__global__ __launch_bounds__(256) void k_pmax(float* __restrict__ out)
{
    int t = blockIdx.x * 256 + threadIdx.x;
    int v = t >> 4, q = t & 15;
    if (v >= NVOX) return;
    int o = g_vout[v];
    if (o == 0) return;
    o--;
    float4 val = __ldg((const float4*)(g_proj + (size_t)v * 64) + q);
    float* ob = out + (size_t)o * 64 + q * 4;
    amaxf(ob + 0, val.x); amaxf(ob + 1, val.y);
    amaxf(ob + 2, val.z); amaxf(ob + 3, val.w);
}

// ---------------- launch ----------------------------------------------------
// Inputs identified by ELEMENT COUNT + first-appearance order (dict order):
//   400000 x4 -> inv0..inv3 ; 800000 x2 -> inv_pts, inv_out ; 25600000 -> x
//   4096 x3 -> W_red, W_fcs, W_lin2 ; 8192 x2 -> W_att, W_lin1
//   64 x2 -> b_red, b_lin2 ; 128 x2 -> b_att, b_fcs ; 1024 -> W_fc ; 2048 -> W_out
extern "C" void kernel_launch(void* const* d_in, const int* in_sizes, int n_in,
                              void* d_out, int out_size)
{
    const float *x = 0, *Wred = 0, *bred = 0, *Watt = 0, *batt = 0;
    const float *Wfcs = 0, *bfcs = 0, *Wfc = 0, *Wout = 0, *W1 = 0, *W2 = 0, *b2 = 0;
    const int *i0 = 0, *i1 = 0, *i2 = 0, *i3 = 0, *invp = 0, *invo = 0;

    int c400k = 0, c800k = 0, c4096 = 0, c8192 = 0, c64 = 0, c128 = 0;
    for (int i = 0; i < n_in; i++) {
        int s = in_sizes[i];
        const void* p = d_in[i];
        switch (s) {
            case 400000:
                if      (c400k == 0) i0 = (const int*)p;
                else if (c400k == 1) i1 = (const int*)p;
                else if (c400k == 2) i2 = (const int*)p;
                else                 i3 = (const int*)p;
                c400k++; break;
            case 800000:
                if (c800k == 0) invp = (const int*)p; else invo = (const int*)p;
                c800k++; break;
            case 25600000: x = (const float*)p; break;
            case 4096:
                if      (c4096 == 0) Wred = (const float*)p;
                else if (c4096 == 1) Wfcs = (const float*)p;
                else                 W2   = (const float*)p;
                c4096++; break;
            case 8192:
                if (c8192 == 0) Watt = (const float*)p; else W1 = (const float*)p;
                c8192++; break;
            case 64:
                if (c64 == 0) bred = (const float*)p; else b2 = (const float*)p;
                c64++; break;
            case 128:
                if (c128 == 0) batt = (const float*)p; else bfcs = (const float*)p;
                c128++; break;
            case 1024: Wfc  = (const float*)p; break;
            case 2048: Wout = (const float*)p; break;
            default: break;   // size-1 scalars ignored
        }
    }

    float* out = (float*)d_out;

    static int smem_set = 0;
    if (!smem_set) {
        cudaFuncSetAttribute(k_fuse, cudaFuncAttributeMaxDynamicSharedMemorySize,
                             FUSE_SMEM_FLOATS * 4);
        smem_set = 1;
    }

    k_fill_out<<<(out_size + 255) / 256, 256>>>(out, out_size);

    k_wc<<<8, 256>>>(Wout, W1);

    k_map<<<(NPTS + 255) / 256, 256>>>(invp, invo);

    k_red<<<(NVOX + 127) / 128, 128>>>(x, Wred, bred, i0, i1, i2, i3);

    k_rw1<<<(NVOX + 255) / 256, 128>>>(W1);

    {
        long long tot = (long long)8 * NVOX;   // 2*NVOX pairs * 4 subs
        k_scale<<<(unsigned)((tot + 255) / 256), 256>>>(Watt, batt);
    }

    k_fuse<<<(NVOX + 255) / 256, 128, FUSE_SMEM_FLOATS * 4>>>(
        Wfc, Wfcs, bfcs, b2, W2, i0, i1, i2, i3);

    k_pmax<<<((size_t)NVOX * 16 + 255) / 256, 256>>>(out);
}

// round 7
// speedup vs baseline: 1.2193x; 1.2193x over previous
#include <cuda_runtime.h>
#include <cstdint>

#define NVOX 400000
#define NPTS 800000

// ---------------- scratch (device globals; zero-initialized at load) -------
__device__ float g_red [(size_t)NVOX * 64];        // relu(x@Wred+b)      102.4 MB
__device__ float g_rW1 [(size_t)NVOX * 64];        // red @ W_lin1[0:64]  102.4 MB
__device__ float g_ssum[(size_t)4 * NVOX * 64];    // segment sums of red 409.6 MB
__device__ float g_cnt [(size_t)4 * NVOX];         // 6.4 MB
__device__ float g_att [(size_t)4 * NVOX * 32];    // 204.8 MB
__device__ float g_proj[(size_t)NVOX * 64];        // 102.4 MB
__device__ int   g_vout[(size_t)NVOX];             // voxel -> out-row+1 (0 = absent)
__device__ float g_Wc  [32 * 64];                  // W_out @ W_lin1[64:128]

__device__ __forceinline__ float sigm(float x) { return 1.f / (1.f + __expf(-x)); }

__device__ __forceinline__ void amaxf(float* a, float v) {
    if (v >= 0.f) atomicMax((int*)a, __float_as_int(v));
    else          atomicMin((unsigned int*)a, __float_as_uint(v));
}

__device__ __forceinline__ void red4(float* p, float a, float b, float c, float d) {
    asm volatile("red.global.add.v4.f32 [%0], {%1,%2,%3,%4};"
                 :: "l"(p), "f"(a), "f"(b), "f"(c), "f"(d) : "memory");
}

// ---------------- init kernels ---------------------------------------------
__global__ void k_fill_out(float* __restrict__ out, int n) {
    int i = blockIdx.x * blockDim.x + threadIdx.x;
    if (i < n) ((unsigned int*)out)[i] = 0xFF800000u;   // -inf
}

// Wc[k][c] = sum_t W_out[k][t] * W_lin1[64+t][c]
__global__ void k_wc(const float* __restrict__ Wout, const float* __restrict__ W1) {
    int idx = blockIdx.x * blockDim.x + threadIdx.x;   // 2048 = 32*64
    if (idx >= 32 * 64) return;
    int k = idx >> 6, c = idx & 63;
    float s = 0.f;
    for (int t = 0; t < 64; t++) s += Wout[k * 64 + t] * W1[(64 + t) * 64 + c];
    g_Wc[idx] = s;
}

// ---------------- K1: red = relu(x@Wred+b); store red; scatter -------------
// Column-split: two 32-col passes keep live accumulators at 32 floats.
__global__ __launch_bounds__(128, 6) void k_red(
    const float* __restrict__ x, const float* __restrict__ W,
    const float* __restrict__ b,
    const int* __restrict__ i0, const int* __restrict__ i1,
    const int* __restrict__ i2, const int* __restrict__ i3)
{
    __shared__ float4 sW[64 * 16];   // 16 KB  W_red [64][64]
    int tid = threadIdx.x;
    for (int i = tid; i < 64 * 16; i += 128) sW[i] = ((const float4*)W)[i];
    __syncthreads();

    int v = blockIdx.x * 128 + tid;
    if (v >= NVOX) return;
    const float4* xr = (const float4*)(x + (size_t)v * 64);
    int sg[4] = {__ldg(i0 + v), __ldg(i1 + v), __ldg(i2 + v), __ldg(i3 + v)};

#pragma unroll
    for (int half = 0; half < 2; half++) {
        float acc[32];
#pragma unroll
        for (int c = 0; c < 32; c++) acc[c] = 0.f;
#pragma unroll
        for (int kq = 0; kq < 16; kq++) {
            float4 x4 = __ldg(xr + kq);
            float xv[4] = {x4.x, x4.y, x4.z, x4.w};
#pragma unroll
            for (int kk = 0; kk < 4; kk++) {
                int k = kq * 4 + kk;
#pragma unroll
                for (int c4 = 0; c4 < 8; c4++) {
                    float4 w = sW[k * 16 + half * 8 + c4];
                    acc[c4 * 4 + 0] += xv[kk] * w.x;
                    acc[c4 * 4 + 1] += xv[kk] * w.y;
                    acc[c4 * 4 + 2] += xv[kk] * w.z;
                    acc[c4 * 4 + 3] += xv[kk] * w.w;
                }
            }
        }
#pragma unroll
        for (int c = 0; c < 32; c++)
            acc[c] = fmaxf(acc[c] + __ldg(b + half * 32 + c), 0.f);

        float4* rr = (float4*)(g_red + (size_t)v * 64) + half * 8;
#pragma unroll
        for (int q = 0; q < 8; q++)
            rr[q] = make_float4(acc[4 * q], acc[4 * q + 1], acc[4 * q + 2], acc[4 * q + 3]);

#pragma unroll
        for (int j = 0; j < 4; j++) {
            float* dst = g_ssum + ((size_t)j * NVOX + sg[j]) * 64 + half * 32;
#pragma unroll
            for (int q = 0; q < 8; q++)
                red4(dst + q * 4, acc[4 * q], acc[4 * q + 1], acc[4 * q + 2], acc[4 * q + 3]);
        }
    }
#pragma unroll
    for (int j = 0; j < 4; j++)
        atomicAdd(g_cnt + (size_t)j * NVOX + sg[j], 1.0f);
}

// ---------------- K1b: rW1 = red @ W1[0:64]  (lean, column-split) ----------
__global__ __launch_bounds__(128, 6) void k_rw1(const float* __restrict__ W1)
{
    __shared__ float4 sW1[64 * 16];   // 16 KB  W_lin1 rows 0..63
    int tid = threadIdx.x;
    for (int i = tid; i < 64 * 16; i += 128) sW1[i] = ((const float4*)W1)[i];
    __syncthreads();

    int v = blockIdx.x * 128 + tid;
    if (v >= NVOX) return;
    const float4* rp = (const float4*)(g_red + (size_t)v * 64);

#pragma unroll
    for (int half = 0; half < 2; half++) {
        float acc[32];
#pragma unroll
        for (int c = 0; c < 32; c++) acc[c] = 0.f;
#pragma unroll
        for (int kq = 0; kq < 16; kq++) {
            float4 x4 = __ldg(rp + kq);
            float xv[4] = {x4.x, x4.y, x4.z, x4.w};
#pragma unroll
            for (int kk = 0; kk < 4; kk++) {
                int k = kq * 4 + kk;
#pragma unroll
                for (int c4 = 0; c4 < 8; c4++) {
                    float4 w = sW1[k * 16 + half * 8 + c4];
                    acc[c4 * 4 + 0] += xv[kk] * w.x;
                    acc[c4 * 4 + 1] += xv[kk] * w.y;
                    acc[c4 * 4 + 2] += xv[kk] * w.z;
                    acc[c4 * 4 + 3] += xv[kk] * w.w;
                }
            }
        }
        float4* orow = (float4*)(g_rW1 + (size_t)v * 64) + half * 8;
#pragma unroll
        for (int q = 0; q < 8; q++)
            orow[q] = make_float4(acc[4 * q], acc[4 * q + 1], acc[4 * q + 2], acc[4 * q + 3]);
    }
}

// ---------------- K2: att = relu((ssum/cnt)@W_att + b); self-clean ---------
// 4 threads per segment row; thread sub computes output cols [sub*8, sub*8+8)
__global__ __launch_bounds__(256) void k_scale(
    const float* __restrict__ Watt, const float* __restrict__ batt)
{
    __shared__ float4 sA[4 * 64 * 8];   // 32 KB all 4 scales [j][k][32]
    int tid = threadIdx.x;
    for (int i = tid; i < 4 * 64 * 8; i += 256)
        sA[i] = ((const float4*)Watt)[i];
    __syncthreads();

    long long t = (long long)blockIdx.x * 256 + tid;     // 4*NVOX*4 threads
    long long row = t >> 2;
    int sub = (int)(t & 3);
    if (row >= (long long)4 * NVOX) return;
    int j = (int)(row / NVOX);
    float c = g_cnt[row];
    if (c != 0.f) {
        float invc = 1.f / c;
        float4* sp = (float4*)(g_ssum + row * 64);

        float a[8];
#pragma unroll
        for (int i = 0; i < 8; i++) a[i] = 0.f;
#pragma unroll
        for (int kq = 0; kq < 16; kq++) {
            float4 x4 = __ldg(sp + kq);
            float xv[4] = {x4.x * invc, x4.y * invc, x4.z * invc, x4.w * invc};
#pragma unroll
            for (int kk = 0; kk < 4; kk++) {
                int k = kq * 4 + kk;
                float4 w0 = sA[(j * 64 + k) * 8 + sub * 2 + 0];
                float4 w1 = sA[(j * 64 + k) * 8 + sub * 2 + 1];
                a[0] += xv[kk] * w0.x; a[1] += xv[kk] * w0.y;
                a[2] += xv[kk] * w0.z; a[3] += xv[kk] * w0.w;
                a[4] += xv[kk] * w1.x; a[5] += xv[kk] * w1.y;
                a[6] += xv[kk] * w1.z; a[7] += xv[kk] * w1.w;
            }
        }
        float4* op = (float4*)(g_att + row * 32) + sub * 2;
        float4 o0, o1;
        o0.x = fmaxf(a[0] + __ldg(batt + j * 32 + sub * 8 + 0), 0.f);
        o0.y = fmaxf(a[1] + __ldg(batt + j * 32 + sub * 8 + 1), 0.f);
        o0.z = fmaxf(a[2] + __ldg(batt + j * 32 + sub * 8 + 2), 0.f);
        o0.w = fmaxf(a[3] + __ldg(batt + j * 32 + sub * 8 + 3), 0.f);
        o1.x = fmaxf(a[4] + __ldg(batt + j * 32 + sub * 8 + 4), 0.f);
        o1.y = fmaxf(a[5] + __ldg(batt + j * 32 + sub * 8 + 5), 0.f);
        o1.z = fmaxf(a[6] + __ldg(batt + j * 32 + sub * 8 + 6), 0.f);
        o1.w = fmaxf(a[7] + __ldg(batt + j * 32 + sub * 8 + 7), 0.f);
        op[0] = o0; op[1] = o1;

        // self-clean ssum quarter (4 float4 each thread)
        float4 z = make_float4(0.f, 0.f, 0.f, 0.f);
#pragma unroll
        for (int q = 0; q < 4; q++) sp[sub * 4 + q] = z;
    }
    __syncwarp();                           // all 4 readers of cnt done
    if (c != 0.f && sub == 0) g_cnt[row] = 0.f;
}

// ---------------- K3: fusion + attention + MLP per voxel -> proj -----------
__global__ __launch_bounds__(256, 2) void k_fuse(
    const float* __restrict__ Wfc,  const float* __restrict__ Wfcs,
    const float* __restrict__ bfcs, const float* __restrict__ W2,
    const float* __restrict__ b2,
    const int* __restrict__ i0, const int* __restrict__ i1,
    const int* __restrict__ i2, const int* __restrict__ i3)
{
    __shared__ float4 sWfcs[4 * 32 * 8];   // 16 KB
    __shared__ float4 sWc  [32 * 16];      // 8 KB
    __shared__ float4 sW2  [64 * 16];      // 16 KB
    __shared__ float4 sWfc [32 * 8];       // 4 KB
    __shared__ float  sbfcs[4 * 32];
    __shared__ float  sb2  [64];

    int tid = threadIdx.x;
    for (int i = tid; i < 1024; i += 256) sWfcs[i] = ((const float4*)Wfcs)[i];
    for (int i = tid; i < 512;  i += 256) sWc[i]   = ((const float4*)g_Wc)[i];
    for (int i = tid; i < 1024; i += 256) sW2[i]   = ((const float4*)W2)[i];
    for (int i = tid; i < 256;  i += 256) sWfc[i]  = ((const float4*)Wfc)[i];
    if (tid < 128) sbfcs[tid] = bfcs[tid];
    if (tid < 64)  sb2[tid]   = b2[tid];
    __syncthreads();

    int v = blockIdx.x * 256 + tid;
    if (v >= NVOX) return;
    int sg[4] = {__ldg(i0 + v), __ldg(i1 + v), __ldg(i2 + v), __ldg(i3 + v)};

    // feat_S = sum_j s_j
    float fS[32];
#pragma unroll
    for (int i = 0; i < 32; i++) fS[i] = 0.f;
#pragma unroll
    for (int j = 0; j < 4; j++) {
        const float4* sp = (const float4*)(g_att + ((size_t)j * NVOX + sg[j]) * 32);
#pragma unroll
        for (int q = 0; q < 8; q++) {
            float4 s4 = __ldg(sp + q);
            fS[4 * q + 0] += s4.x; fS[4 * q + 1] += s4.y;
            fS[4 * q + 2] += s4.z; fS[4 * q + 3] += s4.w;
        }
    }

    // feat_Z = relu(feat_S @ W_fc)
    float fZ[32];
#pragma unroll
    for (int i = 0; i < 32; i++) fZ[i] = 0.f;
#pragma unroll
    for (int k = 0; k < 32; k++) {
        float xv = fS[k];
#pragma unroll
        for (int c4 = 0; c4 < 8; c4++) {
            float4 w = sWfc[k * 8 + c4];
            fZ[c4 * 4 + 0] += xv * w.x; fZ[c4 * 4 + 1] += xv * w.y;
            fZ[c4 * 4 + 2] += xv * w.z; fZ[c4 * 4 + 3] += xv * w.w;
        }
    }
#pragma unroll
    for (int i = 0; i < 32; i++) fZ[i] = fmaxf(fZ[i], 0.f);

    // m = sum_j s_j * sigmoid(fZ @ W_fcs[j] + b_fcs[j])   (re-gather, L1-warm)
    float m[32];
#pragma unroll
    for (int i = 0; i < 32; i++) m[i] = 0.f;
#pragma unroll
    for (int j = 0; j < 4; j++) {
        const float4* sp = (const float4*)(g_att + ((size_t)j * NVOX + sg[j]) * 32);
#pragma unroll
        for (int c4 = 0; c4 < 8; c4++) {
            float a0 = sbfcs[j * 32 + 4 * c4 + 0];
            float a1 = sbfcs[j * 32 + 4 * c4 + 1];
            float a2 = sbfcs[j * 32 + 4 * c4 + 2];
            float a3 = sbfcs[j * 32 + 4 * c4 + 3];
#pragma unroll
            for (int k = 0; k < 32; k++) {
                float4 w = sWfcs[(j * 32 + k) * 8 + c4];
                a0 += fZ[k] * w.x; a1 += fZ[k] * w.y;
                a2 += fZ[k] * w.z; a3 += fZ[k] * w.w;
            }
            float4 s4 = __ldg(sp + c4);
            m[4 * c4 + 0] += s4.x * sigm(a0);
            m[4 * c4 + 1] += s4.y * sigm(a1);
            m[4 * c4 + 2] += s4.z * sigm(a2);
            m[4 * c4 + 3] += s4.w * sigm(a3);
        }
    }

    // h = relu(rW1 + m @ Wc)
    float h[64];
    const float4* rp = (const float4*)(g_rW1 + (size_t)v * 64);
#pragma unroll
    for (int half = 0; half < 2; half++) {
        float a32[32];
#pragma unroll
        for (int q = 0; q < 8; q++) {
            float4 r4 = __ldg(rp + half * 8 + q);
            a32[4 * q + 0] = r4.x; a32[4 * q + 1] = r4.y;
            a32[4 * q + 2] = r4.z; a32[4 * q + 3] = r4.w;
        }
#pragma unroll
        for (int k = 0; k < 32; k++) {
            float xv = m[k];
#pragma unroll
            for (int c4 = 0; c4 < 8; c4++) {
                float4 w = sWc[k * 16 + half * 8 + c4];
                a32[c4 * 4 + 0] += xv * w.x; a32[c4 * 4 + 1] += xv * w.y;
                a32[c4 * 4 + 2] += xv * w.z; a32[c4 * 4 + 3] += xv * w.w;
            }
        }
#pragma unroll
        for (int c = 0; c < 32; c++) h[half * 32 + c] = fmaxf(a32[c], 0.f);
    }

    // proj = h @ W2 + b2  (two 32-col halves)
    float4* pr = (float4*)(g_proj + (size_t)v * 64);
#pragma unroll
    for (int half = 0; half < 2; half++) {
        float p32[32];
#pragma unroll
        for (int c = 0; c < 32; c++) p32[c] = sb2[half * 32 + c];
#pragma unroll
        for (int k = 0; k < 64; k++) {
            float xv = h[k];
#pragma unroll
            for (int c4 = 0; c4 < 8; c4++) {
                float4 w = sW2[k * 16 + half * 8 + c4];
                p32[c4 * 4 + 0] += xv * w.x; p32[c4 * 4 + 1] += xv * w.y;
                p32[c4 * 4 + 2] += xv * w.z; p32[c4 * 4 + 3] += xv * w.w;
            }
        }
#pragma unroll
        for (int q = 0; q < 8; q++)
            pr[half * 8 + q] = make_float4(p32[4 * q], p32[4 * q + 1],
                                           p32[4 * q + 2], p32[4 * q + 3]);
    }
}

// ---------------- K4a: point -> voxel out-row map (idempotent) --------------
__global__ __launch_bounds__(256) void k_map(
    const int* __restrict__ invp, const int* __restrict__ invo)
{
    int p = blockIdx.x * 256 + threadIdx.x;
    if (p >= NPTS) return;
    g_vout[__ldg(invp + p)] = __ldg(invo + p) + 1;
}

// ---------------- K4b: per present voxel, segment-max proj into out --------
__global__ __launch_bounds__(256) void k_pmax(float* __restrict__ out)
{
    int t = blockIdx.x * 256 + threadIdx.x;
    int v = t >> 4, q = t & 15;
    if (v >= NVOX) return;
    int o = g_vout[v];
    if (o == 0) return;
    o--;
    float4 val = __ldg((const float4*)(g_proj + (size_t)v * 64) + q);
    float* ob = out + (size_t)o * 64 + q * 4;
    amaxf(ob + 0, val.x); amaxf(ob + 1, val.y);
    amaxf(ob + 2, val.z); amaxf(ob + 3, val.w);
}

// ---------------- launch ----------------------------------------------------
// Inputs identified by ELEMENT COUNT + first-appearance order (dict order):
//   400000 x4 -> inv0..inv3 ; 800000 x2 -> inv_pts, inv_out ; 25600000 -> x
//   4096 x3 -> W_red, W_fcs, W_lin2 ; 8192 x2 -> W_att, W_lin1
//   64 x2 -> b_red, b_lin2 ; 128 x2 -> b_att, b_fcs ; 1024 -> W_fc ; 2048 -> W_out
extern "C" void kernel_launch(void* const* d_in, const int* in_sizes, int n_in,
                              void* d_out, int out_size)
{
    const float *x = 0, *Wred = 0, *bred = 0, *Watt = 0, *batt = 0;
    const float *Wfcs = 0, *bfcs = 0, *Wfc = 0, *Wout = 0, *W1 = 0, *W2 = 0, *b2 = 0;
    const int *i0 = 0, *i1 = 0, *i2 = 0, *i3 = 0, *invp = 0, *invo = 0;

    int c400k = 0, c800k = 0, c4096 = 0, c8192 = 0, c64 = 0, c128 = 0;
    for (int i = 0; i < n_in; i++) {
        int s = in_sizes[i];
        const void* p = d_in[i];
        switch (s) {
            case 400000:
                if      (c400k == 0) i0 = (const int*)p;
                else if (c400k == 1) i1 = (const int*)p;
                else if (c400k == 2) i2 = (const int*)p;
                else                 i3 = (const int*)p;
                c400k++; break;
            case 800000:
                if (c800k == 0) invp = (const int*)p; else invo = (const int*)p;
                c800k++; break;
            case 25600000: x = (const float*)p; break;
            case 4096:
                if      (c4096 == 0) Wred = (const float*)p;
                else if (c4096 == 1) Wfcs = (const float*)p;
                else                 W2   = (const float*)p;
                c4096++; break;
            case 8192:
                if (c8192 == 0) Watt = (const float*)p; else W1 = (const float*)p;
                c8192++; break;
            case 64:
                if (c64 == 0) bred = (const float*)p; else b2 = (const float*)p;
                c64++; break;
            case 128:
                if (c128 == 0) batt = (const float*)p; else bfcs = (const float*)p;
                c128++; break;
            case 1024: Wfc  = (const float*)p; break;
            case 2048: Wout = (const float*)p; break;
            default: break;   // size-1 scalars ignored
        }
    }

    float* out = (float*)d_out;

    k_fill_out<<<(out_size + 255) / 256, 256>>>(out, out_size);

    k_wc<<<8, 256>>>(Wout, W1);

    k_map<<<(NPTS + 255) / 256, 256>>>(invp, invo);

    k_red<<<(NVOX + 127) / 128, 128>>>(x, Wred, bred, i0, i1, i2, i3);

    k_rw1<<<(NVOX + 127) / 128, 128>>>(W1);

    {
        long long tot = (long long)4 * NVOX * 4;
        k_scale<<<(unsigned)((tot + 255) / 256), 256>>>(Watt, batt);
    }

    k_fuse<<<(NVOX + 255) / 256, 256>>>(Wfc, Wfcs, bfcs, W2, b2, i0, i1, i2, i3);

    k_pmax<<<((size_t)NVOX * 16 + 255) / 256, 256>>>(out);
}

// round 8
// speedup vs baseline: 1.4104x; 1.1567x over previous
#include <cuda_runtime.h>
#include <cstdint>

#define NVOX 400000
#define NPTS 800000

// ---------------- scratch (device globals; zero-initialized at load) -------
__device__ float g_red [(size_t)NVOX * 64];        // relu(x@Wred+b)      102.4 MB
__device__ float g_rW1 [(size_t)NVOX * 64];        // red @ W_lin1[0:64]  102.4 MB
__device__ float g_ssum[(size_t)4 * NVOX * 64];    // segment sums of red 409.6 MB
__device__ float g_cnt [(size_t)4 * NVOX];         // 6.4 MB
__device__ float g_att [(size_t)4 * NVOX * 32];    // 204.8 MB
__device__ float g_m   [(size_t)NVOX * 32];        // fused attention feat 51.2 MB
__device__ float g_proj[(size_t)NVOX * 64];        // 102.4 MB
__device__ int   g_vout[(size_t)NVOX];             // voxel -> out-row+1 (0 = absent)
__device__ float g_Wc  [32 * 64];                  // W_out @ W_lin1[64:128]

__device__ __forceinline__ float sigm(float x) { return 1.f / (1.f + __expf(-x)); }

__device__ __forceinline__ void amaxf(float* a, float v) {
    if (v >= 0.f) atomicMax((int*)a, __float_as_int(v));
    else          atomicMin((unsigned int*)a, __float_as_uint(v));
}

__device__ __forceinline__ void red4(float* p, float a, float b, float c, float d) {
    asm volatile("red.global.add.v4.f32 [%0], {%1,%2,%3,%4};"
                 :: "l"(p), "f"(a), "f"(b), "f"(c), "f"(d) : "memory");
}

__device__ __forceinline__ unsigned tf32cvt(float f) {
    unsigned u; asm("cvt.rna.tf32.f32 %0, %1;" : "=r"(u) : "f"(f)); return u;
}

__device__ __forceinline__ void mma_tf32(
    float& d0, float& d1, float& d2, float& d3,
    unsigned a0, unsigned a1, unsigned a2, unsigned a3,
    unsigned b0, unsigned b1)
{
    asm volatile(
        "mma.sync.aligned.m16n8k8.row.col.f32.tf32.tf32.f32 "
        "{%0,%1,%2,%3}, {%4,%5,%6,%7}, {%8,%9}, {%0,%1,%2,%3};"
        : "+f"(d0), "+f"(d1), "+f"(d2), "+f"(d3)
        : "r"(a0), "r"(a1), "r"(a2), "r"(a3), "r"(b0), "r"(b1));
}

// ---------------- init kernels ---------------------------------------------
__global__ void k_fill_out(float* __restrict__ out, int n) {
    int i = blockIdx.x * blockDim.x + threadIdx.x;
    if (i < n) ((unsigned int*)out)[i] = 0xFF800000u;   // -inf
}

// Wc[k][c] = sum_t W_out[k][t] * W_lin1[64+t][c]
__global__ void k_wc(const float* __restrict__ Wout, const float* __restrict__ W1) {
    int idx = blockIdx.x * blockDim.x + threadIdx.x;   // 2048 = 32*64
    if (idx >= 32 * 64) return;
    int k = idx >> 6, c = idx & 63;
    float s = 0.f;
    for (int t = 0; t < 64; t++) s += Wout[k * 64 + t] * W1[(64 + t) * 64 + c];
    g_Wc[idx] = s;
}

// ---------------- K1: red = relu(x@Wred+b); scatter red; store red@W1a -----
__global__ __launch_bounds__(128) void k_red(
    const float* __restrict__ x, const float* __restrict__ W,
    const float* __restrict__ b, const float* __restrict__ W1,
    const int* __restrict__ i0, const int* __restrict__ i1,
    const int* __restrict__ i2, const int* __restrict__ i3)
{
    __shared__ float4 sW [64 * 16];   // 16 KB  W_red
    __shared__ float4 sW1[64 * 16];   // 16 KB  W_lin1 rows 0..63
    int tid = threadIdx.x;
    for (int i = tid; i < 64 * 16; i += 128) sW[i]  = ((const float4*)W)[i];
    for (int i = tid; i < 64 * 16; i += 128) sW1[i] = ((const float4*)W1)[i];
    __syncthreads();

    int v = blockIdx.x * 128 + tid;
    if (v >= NVOX) return;
    const float4* xr = (const float4*)(x + (size_t)v * 64);

    float acc[64];
#pragma unroll
    for (int c = 0; c < 64; c++) acc[c] = 0.f;

#pragma unroll
    for (int kq = 0; kq < 16; kq++) {
        float4 x4 = __ldg(xr + kq);
        float xv[4] = {x4.x, x4.y, x4.z, x4.w};
#pragma unroll
        for (int kk = 0; kk < 4; kk++) {
            int k = kq * 4 + kk;
#pragma unroll
            for (int c4 = 0; c4 < 16; c4++) {
                float4 w = sW[k * 16 + c4];
                acc[c4 * 4 + 0] += xv[kk] * w.x;
                acc[c4 * 4 + 1] += xv[kk] * w.y;
                acc[c4 * 4 + 2] += xv[kk] * w.z;
                acc[c4 * 4 + 3] += xv[kk] * w.w;
            }
        }
    }
    float red[64];
#pragma unroll
    for (int c = 0; c < 64; c++) red[c] = fmaxf(acc[c] + __ldg(b + c), 0.f);

    // scatter red into 4 per-scale segment sums
    const int* invs[4] = {i0, i1, i2, i3};
#pragma unroll
    for (int j = 0; j < 4; j++) {
        int s = __ldg(invs[j] + v);
        float* dst = g_ssum + ((size_t)j * NVOX + s) * 64;
#pragma unroll
        for (int q = 0; q < 16; q++)
            red4(dst + q * 4, red[4 * q], red[4 * q + 1], red[4 * q + 2], red[4 * q + 3]);
        atomicAdd(g_cnt + (size_t)j * NVOX + s, 1.0f);
    }

    // rW1 = red @ W1[0:64]  (two 32-col halves to bound register pressure)
    float4* rr = (float4*)(g_rW1 + (size_t)v * 64);
#pragma unroll
    for (int half = 0; half < 2; half++) {
        float a32[32];
#pragma unroll
        for (int c = 0; c < 32; c++) a32[c] = 0.f;
#pragma unroll
        for (int k = 0; k < 64; k++) {
            float xv = red[k];
#pragma unroll
            for (int c4 = 0; c4 < 8; c4++) {
                float4 w = sW1[k * 16 + half * 8 + c4];
                a32[c4 * 4 + 0] += xv * w.x;
                a32[c4 * 4 + 1] += xv * w.y;
                a32[c4 * 4 + 2] += xv * w.z;
                a32[c4 * 4 + 3] += xv * w.w;
            }
        }
#pragma unroll
        for (int q = 0; q < 8; q++)
            rr[half * 8 + q] = make_float4(a32[4 * q], a32[4 * q + 1],
                                           a32[4 * q + 2], a32[4 * q + 3]);
    }
}

// ---------------- K2: att = relu((ssum/cnt)@W_att + b); self-clean ---------
// 4 threads per segment row; thread sub computes output cols [sub*8, sub*8+8)
__global__ __launch_bounds__(256) void k_scale(
    const float* __restrict__ Watt, const float* __restrict__ batt)
{
    __shared__ float4 sA[4 * 64 * 8];   // 32 KB all 4 scales [j][k][32]
    int tid = threadIdx.x;
    for (int i = tid; i < 4 * 64 * 8; i += 256)
        sA[i] = ((const float4*)Watt)[i];
    __syncthreads();

    long long t = (long long)blockIdx.x * 256 + tid;     // 4*NVOX*4 threads
    long long row = t >> 2;
    int sub = (int)(t & 3);
    if (row >= (long long)4 * NVOX) return;
    int j = (int)(row / NVOX);
    float c = g_cnt[row];
    if (c != 0.f) {
        float invc = 1.f / c;
        float4* sp = (float4*)(g_ssum + row * 64);

        float a[8];
#pragma unroll
        for (int i = 0; i < 8; i++) a[i] = 0.f;
#pragma unroll
        for (int kq = 0; kq < 16; kq++) {
            float4 x4 = __ldg(sp + kq);
            float xv[4] = {x4.x * invc, x4.y * invc, x4.z * invc, x4.w * invc};
#pragma unroll
            for (int kk = 0; kk < 4; kk++) {
                int k = kq * 4 + kk;
                float4 w0 = sA[(j * 64 + k) * 8 + sub * 2 + 0];
                float4 w1 = sA[(j * 64 + k) * 8 + sub * 2 + 1];
                a[0] += xv[kk] * w0.x; a[1] += xv[kk] * w0.y;
                a[2] += xv[kk] * w0.z; a[3] += xv[kk] * w0.w;
                a[4] += xv[kk] * w1.x; a[5] += xv[kk] * w1.y;
                a[6] += xv[kk] * w1.z; a[7] += xv[kk] * w1.w;
            }
        }
        float4* op = (float4*)(g_att + row * 32) + sub * 2;
        float4 o0, o1;
        o0.x = fmaxf(a[0] + __ldg(batt + j * 32 + sub * 8 + 0), 0.f);
        o0.y = fmaxf(a[1] + __ldg(batt + j * 32 + sub * 8 + 1), 0.f);
        o0.z = fmaxf(a[2] + __ldg(batt + j * 32 + sub * 8 + 2), 0.f);
        o0.w = fmaxf(a[3] + __ldg(batt + j * 32 + sub * 8 + 3), 0.f);
        o1.x = fmaxf(a[4] + __ldg(batt + j * 32 + sub * 8 + 4), 0.f);
        o1.y = fmaxf(a[5] + __ldg(batt + j * 32 + sub * 8 + 5), 0.f);
        o1.z = fmaxf(a[6] + __ldg(batt + j * 32 + sub * 8 + 6), 0.f);
        o1.w = fmaxf(a[7] + __ldg(batt + j * 32 + sub * 8 + 7), 0.f);
        op[0] = o0; op[1] = o1;

        // self-clean ssum quarter (4 float4 each thread)
        float4 z = make_float4(0.f, 0.f, 0.f, 0.f);
#pragma unroll
        for (int q = 0; q < 4; q++) sp[sub * 4 + q] = z;
    }
    __syncwarp();                           // all 4 readers of cnt done
    if (c != 0.f && sub == 0) g_cnt[row] = 0.f;
}

// ---------------- K3: gather + fZ + sigmoid attention -> m -----------------
__global__ __launch_bounds__(256, 2) void k_fuse2(
    const float* __restrict__ Wfc,  const float* __restrict__ Wfcs,
    const float* __restrict__ bfcs,
    const int* __restrict__ i0, const int* __restrict__ i1,
    const int* __restrict__ i2, const int* __restrict__ i3)
{
    __shared__ float4 sWfcs[4 * 32 * 8];   // 16 KB
    __shared__ float4 sWfc [32 * 8];       // 4 KB
    __shared__ float  sbfcs[4 * 32];

    int tid = threadIdx.x;
    for (int i = tid; i < 1024; i += 256) sWfcs[i] = ((const float4*)Wfcs)[i];
    for (int i = tid; i < 256;  i += 256) sWfc[i]  = ((const float4*)Wfc)[i];
    if (tid < 128) sbfcs[tid] = bfcs[tid];
    __syncthreads();

    int v = blockIdx.x * 256 + tid;
    if (v >= NVOX) return;
    int sg[4] = {__ldg(i0 + v), __ldg(i1 + v), __ldg(i2 + v), __ldg(i3 + v)};

    // feat_S = sum_j s_j
    float fS[32];
#pragma unroll
    for (int i = 0; i < 32; i++) fS[i] = 0.f;
#pragma unroll
    for (int j = 0; j < 4; j++) {
        const float4* sp = (const float4*)(g_att + ((size_t)j * NVOX + sg[j]) * 32);
#pragma unroll
        for (int q = 0; q < 8; q++) {
            float4 s4 = __ldg(sp + q);
            fS[4 * q + 0] += s4.x; fS[4 * q + 1] += s4.y;
            fS[4 * q + 2] += s4.z; fS[4 * q + 3] += s4.w;
        }
    }

    // feat_Z = relu(feat_S @ W_fc)
    float fZ[32];
#pragma unroll
    for (int i = 0; i < 32; i++) fZ[i] = 0.f;
#pragma unroll
    for (int k = 0; k < 32; k++) {
        float xv = fS[k];
#pragma unroll
        for (int c4 = 0; c4 < 8; c4++) {
            float4 w = sWfc[k * 8 + c4];
            fZ[c4 * 4 + 0] += xv * w.x; fZ[c4 * 4 + 1] += xv * w.y;
            fZ[c4 * 4 + 2] += xv * w.z; fZ[c4 * 4 + 3] += xv * w.w;
        }
    }
#pragma unroll
    for (int i = 0; i < 32; i++) fZ[i] = fmaxf(fZ[i], 0.f);

    // m = sum_j s_j * sigmoid(fZ @ W_fcs[j] + b_fcs[j])   (re-gather, L1-warm)
    float m[32];
#pragma unroll
    for (int i = 0; i < 32; i++) m[i] = 0.f;
#pragma unroll
    for (int j = 0; j < 4; j++) {
        const float4* sp = (const float4*)(g_att + ((size_t)j * NVOX + sg[j]) * 32);
#pragma unroll
        for (int c4 = 0; c4 < 8; c4++) {
            float a0 = sbfcs[j * 32 + 4 * c4 + 0];
            float a1 = sbfcs[j * 32 + 4 * c4 + 1];
            float a2 = sbfcs[j * 32 + 4 * c4 + 2];
            float a3 = sbfcs[j * 32 + 4 * c4 + 3];
#pragma unroll
            for (int k = 0; k < 32; k++) {
                float4 w = sWfcs[(j * 32 + k) * 8 + c4];
                a0 += fZ[k] * w.x; a1 += fZ[k] * w.y;
                a2 += fZ[k] * w.z; a3 += fZ[k] * w.w;
            }
            float4 s4 = __ldg(sp + c4);
            m[4 * c4 + 0] += s4.x * sigm(a0);
            m[4 * c4 + 1] += s4.y * sigm(a1);
            m[4 * c4 + 2] += s4.z * sigm(a2);
            m[4 * c4 + 3] += s4.w * sigm(a3);
        }
    }

    float4* mo = (float4*)(g_m + (size_t)v * 32);
#pragma unroll
    for (int q = 0; q < 8; q++)
        mo[q] = make_float4(m[4 * q], m[4 * q + 1], m[4 * q + 2], m[4 * q + 3]);
}

// ---------------- K3b: tf32 mma: h=relu(rW1+m@Wc); proj=h@W2+b2 ------------
// 128 threads = 4 warps; each warp owns 16 voxels. NVOX = 16*25000 exactly.
__global__ __launch_bounds__(128) void k_out(
    const float* __restrict__ W2, const float* __restrict__ b2)
{
    __shared__ unsigned sWc[32 * 64];      // 8 KB  (tf32 bits, row-major [k][n])
    __shared__ unsigned sW2[64 * 64];      // 16 KB
    __shared__ float    sb2[64];
    __shared__ float    stage[4][16 * 64]; // 16 KB  per-warp staging (m then h)

    int tid = threadIdx.x;
    for (int i = tid; i < 2048; i += 128) sWc[i] = tf32cvt(g_Wc[i]);
    for (int i = tid; i < 4096; i += 128) sW2[i] = tf32cvt(__ldg(W2 + i));
    if (tid < 64) sb2[tid] = b2[tid];
    __syncthreads();

    int warp = tid >> 5, lane = tid & 31;
    int g  = lane >> 2;          // group row 0..7
    int tg = lane & 3;           // thread-in-group 0..3
    int vbase = (blockIdx.x * 4 + warp) * 16;
    float* st = stage[warp];

    // stage m tile [16][32] (coalesced float4: 128 float4 per warp)
    {
        const float4* msrc = (const float4*)(g_m + (size_t)vbase * 32);
        float4* mdst = (float4*)st;
#pragma unroll
        for (int i = 0; i < 4; i++) mdst[lane + i * 32] = __ldg(msrc + lane + i * 32);
    }
    __syncwarp();

    // A fragments for m (K=32 -> 4 k-tiles)
    unsigned am[4][4];
#pragma unroll
    for (int kt = 0; kt < 4; kt++) {
        am[kt][0] = tf32cvt(st[g * 32       + kt * 8 + tg]);
        am[kt][1] = tf32cvt(st[(g + 8) * 32 + kt * 8 + tg]);
        am[kt][2] = tf32cvt(st[g * 32       + kt * 8 + tg + 4]);
        am[kt][3] = tf32cvt(st[(g + 8) * 32 + kt * 8 + tg + 4]);
    }
    __syncwarp();   // done reading m from stage; reuse it for h

    // h = relu(rW1 + m @ Wc), staged to smem [16][64]
    const float* rbase = g_rW1 + (size_t)vbase * 64;
#pragma unroll
    for (int nt = 0; nt < 8; nt++) {
        float2 c01 = *(const float2*)(rbase + (size_t)g * 64       + nt * 8 + 2 * tg);
        float2 c23 = *(const float2*)(rbase + (size_t)(g + 8) * 64 + nt * 8 + 2 * tg);
        float d0 = c01.x, d1 = c01.y, d2 = c23.x, d3 = c23.y;
#pragma unroll
        for (int kt = 0; kt < 4; kt++) {
            unsigned b0 = sWc[(kt * 8 + tg) * 64     + nt * 8 + g];
            unsigned b1 = sWc[(kt * 8 + tg + 4) * 64 + nt * 8 + g];
            mma_tf32(d0, d1, d2, d3, am[kt][0], am[kt][1], am[kt][2], am[kt][3], b0, b1);
        }
        *(float2*)(st + g * 64       + nt * 8 + 2 * tg) =
            make_float2(fmaxf(d0, 0.f), fmaxf(d1, 0.f));
        *(float2*)(st + (g + 8) * 64 + nt * 8 + 2 * tg) =
            make_float2(fmaxf(d2, 0.f), fmaxf(d3, 0.f));
    }
    __syncwarp();

    // A fragments for h (K=64 -> 8 k-tiles)
    unsigned ah[8][4];
#pragma unroll
    for (int kt = 0; kt < 8; kt++) {
        ah[kt][0] = tf32cvt(st[g * 64       + kt * 8 + tg]);
        ah[kt][1] = tf32cvt(st[(g + 8) * 64 + kt * 8 + tg]);
        ah[kt][2] = tf32cvt(st[g * 64       + kt * 8 + tg + 4]);
        ah[kt][3] = tf32cvt(st[(g + 8) * 64 + kt * 8 + tg + 4]);
    }

    // proj = h @ W2 + b2 -> g_proj
    float* pbase = g_proj + (size_t)vbase * 64;
#pragma unroll
    for (int nt = 0; nt < 8; nt++) {
        float bb0 = sb2[nt * 8 + 2 * tg], bb1 = sb2[nt * 8 + 2 * tg + 1];
        float d0 = bb0, d1 = bb1, d2 = bb0, d3 = bb1;
#pragma unroll
        for (int kt = 0; kt < 8; kt++) {
            unsigned b0 = sW2[(kt * 8 + tg) * 64     + nt * 8 + g];
            unsigned b1 = sW2[(kt * 8 + tg + 4) * 64 + nt * 8 + g];
            mma_tf32(d0, d1, d2, d3, ah[kt][0], ah[kt][1], ah[kt][2], ah[kt][3], b0, b1);
        }
        *(float2*)(pbase + (size_t)g * 64       + nt * 8 + 2 * tg) = make_float2(d0, d1);
        *(float2*)(pbase + (size_t)(g + 8) * 64 + nt * 8 + 2 * tg) = make_float2(d2, d3);
    }
}

// ---------------- K4a: point -> voxel out-row map (idempotent) --------------
__global__ __launch_bounds__(256) void k_map(
    const int* __restrict__ invp, const int* __restrict__ invo)
{
    int p = blockIdx.x * 256 + threadIdx.x;
    if (p >= NPTS) return;
    g_vout[__ldg(invp + p)] = __ldg(invo + p) + 1;
}

// ---------------- K4b: per present voxel, segment-max proj into out --------
__global__ __launch_bounds__(256) void k_pmax(float* __restrict__ out)
{
    int t = blockIdx.x * 256 + threadIdx.x;
    int v = t >> 4, q = t & 15;
    if (v >= NVOX) return;
    int o = g_vout[v];
    if (o == 0) return;
    o--;
    float4 val = __ldg((const float4*)(g_proj + (size_t)v * 64) + q);
    float* ob = out + (size_t)o * 64 + q * 4;
    amaxf(ob + 0, val.x); amaxf(ob + 1, val.y);
    amaxf(ob + 2, val.z); amaxf(ob + 3, val.w);
}

// ---------------- launch ----------------------------------------------------
// Inputs identified by ELEMENT COUNT + first-appearance order (dict order):
//   400000 x4 -> inv0..inv3 ; 800000 x2 -> inv_pts, inv_out ; 25600000 -> x
//   4096 x3 -> W_red, W_fcs, W_lin2 ; 8192 x2 -> W_att, W_lin1
//   64 x2 -> b_red, b_lin2 ; 128 x2 -> b_att, b_fcs ; 1024 -> W_fc ; 2048 -> W_out
extern "C" void kernel_launch(void* const* d_in, const int* in_sizes, int n_in,
                              void* d_out, int out_size)
{
    const float *x = 0, *Wred = 0, *bred = 0, *Watt = 0, *batt = 0;
    const float *Wfcs = 0, *bfcs = 0, *Wfc = 0, *Wout = 0, *W1 = 0, *W2 = 0, *b2 = 0;
    const int *i0 = 0, *i1 = 0, *i2 = 0, *i3 = 0, *invp = 0, *invo = 0;

    int c400k = 0, c800k = 0, c4096 = 0, c8192 = 0, c64 = 0, c128 = 0;
    for (int i = 0; i < n_in; i++) {
        int s = in_sizes[i];
        const void* p = d_in[i];
        switch (s) {
            case 400000:
                if      (c400k == 0) i0 = (const int*)p;
                else if (c400k == 1) i1 = (const int*)p;
                else if (c400k == 2) i2 = (const int*)p;
                else                 i3 = (const int*)p;
                c400k++; break;
            case 800000:
                if (c800k == 0) invp = (const int*)p; else invo = (const int*)p;
                c800k++; break;
            case 25600000: x = (const float*)p; break;
            case 4096:
                if      (c4096 == 0) Wred = (const float*)p;
                else if (c4096 == 1) Wfcs = (const float*)p;
                else                 W2   = (const float*)p;
                c4096++; break;
            case 8192:
                if (c8192 == 0) Watt = (const float*)p; else W1 = (const float*)p;
                c8192++; break;
            case 64:
                if (c64 == 0) bred = (const float*)p; else b2 = (const float*)p;
                c64++; break;
            case 128:
                if (c128 == 0) batt = (const float*)p; else bfcs = (const float*)p;
                c128++; break;
            case 1024: Wfc  = (const float*)p; break;
            case 2048: Wout = (const float*)p; break;
            default: break;   // size-1 scalars ignored
        }
    }

    float* out = (float*)d_out;

    k_fill_out<<<(out_size + 255) / 256, 256>>>(out, out_size);

    k_wc<<<8, 256>>>(Wout, W1);

    k_map<<<(NPTS + 255) / 256, 256>>>(invp, invo);

    k_red<<<(NVOX + 127) / 128, 128>>>(x, Wred, bred, W1, i0, i1, i2, i3);

    {
        long long tot = (long long)4 * NVOX * 4;
        k_scale<<<(unsigned)((tot + 255) / 256), 256>>>(Watt, batt);
    }

    k_fuse2<<<(NVOX + 255) / 256, 256>>>(Wfc, Wfcs, bfcs, i0, i1, i2, i3);

    k_out<<<NVOX / 64, 128>>>(W2, b2);   // 400000 = 64 * 6250 exactly

    k_pmax<<<((size_t)NVOX * 16 + 255) / 256, 256>>>(out);
}

// round 9
// speedup vs baseline: 1.6148x; 1.1449x over previous
#include <cuda_runtime.h>
#include <cstdint>

#define NVOX 400000
#define NPTS 800000

// ---------------- scratch (device globals; zero-initialized at load) -------
__device__ float g_rW1 [(size_t)NVOX * 64];        // red @ W_lin1[0:64]  102.4 MB
__device__ float g_ssum[(size_t)4 * NVOX * 64];    // segment sums of red 409.6 MB
__device__ float g_cnt [(size_t)4 * NVOX];         // 6.4 MB
__device__ float g_att [(size_t)4 * NVOX * 32];    // 204.8 MB
__device__ float g_m   [(size_t)NVOX * 32];        // fused attention feat 51.2 MB
__device__ float g_proj[(size_t)NVOX * 64];        // 102.4 MB
__device__ int   g_vout[(size_t)NVOX];             // voxel -> out-row+1 (0 = absent)
__device__ float g_Wc  [32 * 64];                  // W_out @ W_lin1[64:128]

__device__ __forceinline__ float sigm(float x) { return 1.f / (1.f + __expf(-x)); }

__device__ __forceinline__ void amaxf(float* a, float v) {
    if (v >= 0.f) atomicMax((int*)a, __float_as_int(v));
    else          atomicMin((unsigned int*)a, __float_as_uint(v));
}

__device__ __forceinline__ void red4(float* p, float a, float b, float c, float d) {
    asm volatile("red.global.add.v4.f32 [%0], {%1,%2,%3,%4};"
                 :: "l"(p), "f"(a), "f"(b), "f"(c), "f"(d) : "memory");
}

__device__ __forceinline__ unsigned tf32cvt(float f) {
    unsigned u; asm("cvt.rna.tf32.f32 %0, %1;" : "=r"(u) : "f"(f)); return u;
}

__device__ __forceinline__ void mma_tf32(
    float& d0, float& d1, float& d2, float& d3,
    unsigned a0, unsigned a1, unsigned a2, unsigned a3,
    unsigned b0, unsigned b1)
{
    asm volatile(
        "mma.sync.aligned.m16n8k8.row.col.f32.tf32.tf32.f32 "
        "{%0,%1,%2,%3}, {%4,%5,%6,%7}, {%8,%9}, {%0,%1,%2,%3};"
        : "+f"(d0), "+f"(d1), "+f"(d2), "+f"(d3)
        : "r"(a0), "r"(a1), "r"(a2), "r"(a3), "r"(b0), "r"(b1));
}

// ---------------- init kernels ---------------------------------------------
__global__ void k_fill_out(float* __restrict__ out, int n) {
    int i = blockIdx.x * blockDim.x + threadIdx.x;
    if (i < n) ((unsigned int*)out)[i] = 0xFF800000u;   // -inf
}

// Wc[k][c] = sum_t W_out[k][t] * W_lin1[64+t][c]
__global__ void k_wc(const float* __restrict__ Wout, const float* __restrict__ W1) {
    int idx = blockIdx.x * blockDim.x + threadIdx.x;   // 2048 = 32*64
    if (idx >= 32 * 64) return;
    int k = idx >> 6, c = idx & 63;
    float s = 0.f;
    for (int t = 0; t < 64; t++) s += Wout[k * 64 + t] * W1[(64 + t) * 64 + c];
    g_Wc[idx] = s;
}

// ---------------- K1: tf32 MMA: red=relu(x@Wred+b); rW1=red@W1a; scatter ---
// 128 thr = 4 warps, 16 voxels/warp, 64 voxels/block. NVOX = 64*6250 exactly.
// dynamic smem (units of 4B): [0,4096) Wred tf32 ; [4096,8192) W1a tf32 ;
//   [8192,8256) bred ; [8256,12608) stage 4 warps x [16][68] floats
#define REDMMA_SMEM_BYTES (12608 * 4)
__global__ __launch_bounds__(128) void k_redmma(
    const float* __restrict__ x, const float* __restrict__ W,
    const float* __restrict__ b, const float* __restrict__ W1,
    const int* __restrict__ i0, const int* __restrict__ i1,
    const int* __restrict__ i2, const int* __restrict__ i3)
{
    extern __shared__ unsigned dsm[];
    unsigned* sWred = dsm;
    unsigned* sW1   = dsm + 4096;
    float*    sbred = (float*)(dsm + 8192);
    float*    stage = (float*)(dsm + 8256);

    int tid = threadIdx.x;
    for (int i = tid; i < 4096; i += 128) sWred[i] = tf32cvt(__ldg(W  + i));
    for (int i = tid; i < 4096; i += 128) sW1[i]   = tf32cvt(__ldg(W1 + i));
    if (tid < 64) sbred[tid] = b[tid];
    __syncthreads();

    int warp = tid >> 5, lane = tid & 31;
    int g  = lane >> 2;          // 0..7
    int tg = lane & 3;           // 0..3
    int vbase = (blockIdx.x * 4 + warp) * 16;
    float* st = stage + warp * 1088;     // [16][68]

    // 1) stage x tile [16][64] (row stride 68 floats = conflict-free frags)
    {
        const float4* xsrc = (const float4*)(x + (size_t)vbase * 64);
#pragma unroll
        for (int i = 0; i < 8; i++) {
            int idx = lane + i * 32;             // 0..255
            int row = idx >> 4, c4 = idx & 15;
            *(float4*)(st + row * 68 + c4 * 4) = __ldg(xsrc + idx);
        }
    }
    __syncwarp();

    // 2) A fragments for x (K=64 -> 8 k-tiles)
    unsigned a[8][4];
#pragma unroll
    for (int kt = 0; kt < 8; kt++) {
        a[kt][0] = tf32cvt(st[g * 68       + kt * 8 + tg]);
        a[kt][1] = tf32cvt(st[(g + 8) * 68 + kt * 8 + tg]);
        a[kt][2] = tf32cvt(st[g * 68       + kt * 8 + tg + 4]);
        a[kt][3] = tf32cvt(st[(g + 8) * 68 + kt * 8 + tg + 4]);
    }
    __syncwarp();   // stage will be overwritten with red

    // 3) red = relu(x @ Wred + b) -> stage
#pragma unroll
    for (int nt = 0; nt < 8; nt++) {
        float d0 = sbred[nt * 8 + 2 * tg], d1 = sbred[nt * 8 + 2 * tg + 1];
        float d2 = d0, d3 = d1;
#pragma unroll
        for (int kt = 0; kt < 8; kt++) {
            unsigned b0 = sWred[(kt * 8 + tg) * 64     + nt * 8 + g];
            unsigned b1 = sWred[(kt * 8 + tg + 4) * 64 + nt * 8 + g];
            mma_tf32(d0, d1, d2, d3, a[kt][0], a[kt][1], a[kt][2], a[kt][3], b0, b1);
        }
        *(float2*)(st + g * 68       + nt * 8 + 2 * tg) =
            make_float2(fmaxf(d0, 0.f), fmaxf(d1, 0.f));
        *(float2*)(st + (g + 8) * 68 + nt * 8 + 2 * tg) =
            make_float2(fmaxf(d2, 0.f), fmaxf(d3, 0.f));
    }
    __syncwarp();

    // 4) A fragments for red
#pragma unroll
    for (int kt = 0; kt < 8; kt++) {
        a[kt][0] = tf32cvt(st[g * 68       + kt * 8 + tg]);
        a[kt][1] = tf32cvt(st[(g + 8) * 68 + kt * 8 + tg]);
        a[kt][2] = tf32cvt(st[g * 68       + kt * 8 + tg + 4]);
        a[kt][3] = tf32cvt(st[(g + 8) * 68 + kt * 8 + tg + 4]);
    }

    // 5) rW1 = red @ W1[0:64] -> global
    float* rbase = g_rW1 + (size_t)vbase * 64;
#pragma unroll
    for (int nt = 0; nt < 8; nt++) {
        float d0 = 0.f, d1 = 0.f, d2 = 0.f, d3 = 0.f;
#pragma unroll
        for (int kt = 0; kt < 8; kt++) {
            unsigned b0 = sW1[(kt * 8 + tg) * 64     + nt * 8 + g];
            unsigned b1 = sW1[(kt * 8 + tg + 4) * 64 + nt * 8 + g];
            mma_tf32(d0, d1, d2, d3, a[kt][0], a[kt][1], a[kt][2], a[kt][3], b0, b1);
        }
        *(float2*)(rbase + (size_t)g * 64       + nt * 8 + 2 * tg) = make_float2(d0, d1);
        *(float2*)(rbase + (size_t)(g + 8) * 64 + nt * 8 + 2 * tg) = make_float2(d2, d3);
    }

    // 6) scatter red into 4 per-scale segment sums (2 lanes per voxel)
    {
        int vox = lane >> 1, half = lane & 1;
        int vv = vbase + vox;
        const float4* srow = (const float4*)(st + vox * 68 + half * 32);
        float4 f[8];
#pragma unroll
        for (int q = 0; q < 8; q++) f[q] = srow[q];

        const int* invs[4] = {i0, i1, i2, i3};
        int sg[4];
#pragma unroll
        for (int j = 0; j < 4; j++) {
            sg[j] = __ldg(invs[j] + vv);
            float* dst = g_ssum + ((size_t)j * NVOX + sg[j]) * 64 + half * 32;
#pragma unroll
            for (int q = 0; q < 8; q++)
                red4(dst + q * 4, f[q].x, f[q].y, f[q].z, f[q].w);
        }
        if (half == 0) {
#pragma unroll
            for (int j = 0; j < 4; j++)
                atomicAdd(g_cnt + (size_t)j * NVOX + sg[j], 1.0f);
        }
    }
}

// ---------------- K2: att = relu((ssum/cnt)@W_att + b); self-clean ---------
__global__ __launch_bounds__(256) void k_scale(
    const float* __restrict__ Watt, const float* __restrict__ batt)
{
    __shared__ float4 sA[4 * 64 * 8];   // 32 KB all 4 scales [j][k][32]
    int tid = threadIdx.x;
    for (int i = tid; i < 4 * 64 * 8; i += 256)
        sA[i] = ((const float4*)Watt)[i];
    __syncthreads();

    long long t = (long long)blockIdx.x * 256 + tid;     // 4*NVOX*4 threads
    long long row = t >> 2;
    int sub = (int)(t & 3);
    if (row >= (long long)4 * NVOX) return;
    int j = (int)(row / NVOX);
    float c = g_cnt[row];
    if (c != 0.f) {
        float invc = 1.f / c;
        float4* sp = (float4*)(g_ssum + row * 64);

        float a[8];
#pragma unroll
        for (int i = 0; i < 8; i++) a[i] = 0.f;
#pragma unroll
        for (int kq = 0; kq < 16; kq++) {
            float4 x4 = __ldg(sp + kq);
            float xv[4] = {x4.x * invc, x4.y * invc, x4.z * invc, x4.w * invc};
#pragma unroll
            for (int kk = 0; kk < 4; kk++) {
                int k = kq * 4 + kk;
                float4 w0 = sA[(j * 64 + k) * 8 + sub * 2 + 0];
                float4 w1 = sA[(j * 64 + k) * 8 + sub * 2 + 1];
                a[0] += xv[kk] * w0.x; a[1] += xv[kk] * w0.y;
                a[2] += xv[kk] * w0.z; a[3] += xv[kk] * w0.w;
                a[4] += xv[kk] * w1.x; a[5] += xv[kk] * w1.y;
                a[6] += xv[kk] * w1.z; a[7] += xv[kk] * w1.w;
            }
        }
        float4* op = (float4*)(g_att + row * 32) + sub * 2;
        float4 o0, o1;
        o0.x = fmaxf(a[0] + __ldg(batt + j * 32 + sub * 8 + 0), 0.f);
        o0.y = fmaxf(a[1] + __ldg(batt + j * 32 + sub * 8 + 1), 0.f);
        o0.z = fmaxf(a[2] + __ldg(batt + j * 32 + sub * 8 + 2), 0.f);
        o0.w = fmaxf(a[3] + __ldg(batt + j * 32 + sub * 8 + 3), 0.f);
        o1.x = fmaxf(a[4] + __ldg(batt + j * 32 + sub * 8 + 4), 0.f);
        o1.y = fmaxf(a[5] + __ldg(batt + j * 32 + sub * 8 + 5), 0.f);
        o1.z = fmaxf(a[6] + __ldg(batt + j * 32 + sub * 8 + 6), 0.f);
        o1.w = fmaxf(a[7] + __ldg(batt + j * 32 + sub * 8 + 7), 0.f);
        op[0] = o0; op[1] = o1;

        float4 z = make_float4(0.f, 0.f, 0.f, 0.f);
#pragma unroll
        for (int q = 0; q < 4; q++) sp[sub * 4 + q] = z;
    }
    __syncwarp();
    if (c != 0.f && sub == 0) g_cnt[row] = 0.f;
}

// ---------------- K3: gather + fZ + sigmoid attention -> m -----------------
__global__ __launch_bounds__(256, 2) void k_fuse2(
    const float* __restrict__ Wfc,  const float* __restrict__ Wfcs,
    const float* __restrict__ bfcs,
    const int* __restrict__ i0, const int* __restrict__ i1,
    const int* __restrict__ i2, const int* __restrict__ i3)
{
    __shared__ float4 sWfcs[4 * 32 * 8];   // 16 KB
    __shared__ float4 sWfc [32 * 8];       // 4 KB
    __shared__ float  sbfcs[4 * 32];

    int tid = threadIdx.x;
    for (int i = tid; i < 1024; i += 256) sWfcs[i] = ((const float4*)Wfcs)[i];
    for (int i = tid; i < 256;  i += 256) sWfc[i]  = ((const float4*)Wfc)[i];
    if (tid < 128) sbfcs[tid] = bfcs[tid];
    __syncthreads();

    int v = blockIdx.x * 256 + tid;
    if (v >= NVOX) return;
    int sg[4] = {__ldg(i0 + v), __ldg(i1 + v), __ldg(i2 + v), __ldg(i3 + v)};

    float fS[32];
#pragma unroll
    for (int i = 0; i < 32; i++) fS[i] = 0.f;
#pragma unroll
    for (int j = 0; j < 4; j++) {
        const float4* sp = (const float4*)(g_att + ((size_t)j * NVOX + sg[j]) * 32);
#pragma unroll
        for (int q = 0; q < 8; q++) {
            float4 s4 = __ldg(sp + q);
            fS[4 * q + 0] += s4.x; fS[4 * q + 1] += s4.y;
            fS[4 * q + 2] += s4.z; fS[4 * q + 3] += s4.w;
        }
    }

    float fZ[32];
#pragma unroll
    for (int i = 0; i < 32; i++) fZ[i] = 0.f;
#pragma unroll
    for (int k = 0; k < 32; k++) {
        float xv = fS[k];
#pragma unroll
        for (int c4 = 0; c4 < 8; c4++) {
            float4 w = sWfc[k * 8 + c4];
            fZ[c4 * 4 + 0] += xv * w.x; fZ[c4 * 4 + 1] += xv * w.y;
            fZ[c4 * 4 + 2] += xv * w.z; fZ[c4 * 4 + 3] += xv * w.w;
        }
    }
#pragma unroll
    for (int i = 0; i < 32; i++) fZ[i] = fmaxf(fZ[i], 0.f);

    float m[32];
#pragma unroll
    for (int i = 0; i < 32; i++) m[i] = 0.f;
#pragma unroll
    for (int j = 0; j < 4; j++) {
        const float4* sp = (const float4*)(g_att + ((size_t)j * NVOX + sg[j]) * 32);
#pragma unroll
        for (int c4 = 0; c4 < 8; c4++) {
            float a0 = sbfcs[j * 32 + 4 * c4 + 0];
            float a1 = sbfcs[j * 32 + 4 * c4 + 1];
            float a2 = sbfcs[j * 32 + 4 * c4 + 2];
            float a3 = sbfcs[j * 32 + 4 * c4 + 3];
#pragma unroll
            for (int k = 0; k < 32; k++) {
                float4 w = sWfcs[(j * 32 + k) * 8 + c4];
                a0 += fZ[k] * w.x; a1 += fZ[k] * w.y;
                a2 += fZ[k] * w.z; a3 += fZ[k] * w.w;
            }
            float4 s4 = __ldg(sp + c4);
            m[4 * c4 + 0] += s4.x * sigm(a0);
            m[4 * c4 + 1] += s4.y * sigm(a1);
            m[4 * c4 + 2] += s4.z * sigm(a2);
            m[4 * c4 + 3] += s4.w * sigm(a3);
        }
    }

    float4* mo = (float4*)(g_m + (size_t)v * 32);
#pragma unroll
    for (int q = 0; q < 8; q++)
        mo[q] = make_float4(m[4 * q], m[4 * q + 1], m[4 * q + 2], m[4 * q + 3]);
}

// ---------------- K3b: tf32 mma: h=relu(rW1+m@Wc); proj=h@W2+b2 ------------
__global__ __launch_bounds__(128) void k_out(
    const float* __restrict__ W2, const float* __restrict__ b2)
{
    __shared__ unsigned sWc[32 * 64];      // 8 KB
    __shared__ unsigned sW2[64 * 64];      // 16 KB
    __shared__ float    sb2[64];
    __shared__ float    stage[4][16 * 64]; // 16 KB

    int tid = threadIdx.x;
    for (int i = tid; i < 2048; i += 128) sWc[i] = tf32cvt(g_Wc[i]);
    for (int i = tid; i < 4096; i += 128) sW2[i] = tf32cvt(__ldg(W2 + i));
    if (tid < 64) sb2[tid] = b2[tid];
    __syncthreads();

    int warp = tid >> 5, lane = tid & 31;
    int g  = lane >> 2;
    int tg = lane & 3;
    int vbase = (blockIdx.x * 4 + warp) * 16;
    float* st = stage[warp];

    {
        const float4* msrc = (const float4*)(g_m + (size_t)vbase * 32);
        float4* mdst = (float4*)st;
#pragma unroll
        for (int i = 0; i < 4; i++) mdst[lane + i * 32] = __ldg(msrc + lane + i * 32);
    }
    __syncwarp();

    unsigned am[4][4];
#pragma unroll
    for (int kt = 0; kt < 4; kt++) {
        am[kt][0] = tf32cvt(st[g * 32       + kt * 8 + tg]);
        am[kt][1] = tf32cvt(st[(g + 8) * 32 + kt * 8 + tg]);
        am[kt][2] = tf32cvt(st[g * 32       + kt * 8 + tg + 4]);
        am[kt][3] = tf32cvt(st[(g + 8) * 32 + kt * 8 + tg + 4]);
    }
    __syncwarp();

    const float* rbase = g_rW1 + (size_t)vbase * 64;
#pragma unroll
    for (int nt = 0; nt < 8; nt++) {
        float2 c01 = *(const float2*)(rbase + (size_t)g * 64       + nt * 8 + 2 * tg);
        float2 c23 = *(const float2*)(rbase + (size_t)(g + 8) * 64 + nt * 8 + 2 * tg);
        float d0 = c01.x, d1 = c01.y, d2 = c23.x, d3 = c23.y;
#pragma unroll
        for (int kt = 0; kt < 4; kt++) {
            unsigned b0 = sWc[(kt * 8 + tg) * 64     + nt * 8 + g];
            unsigned b1 = sWc[(kt * 8 + tg + 4) * 64 + nt * 8 + g];
            mma_tf32(d0, d1, d2, d3, am[kt][0], am[kt][1], am[kt][2], am[kt][3], b0, b1);
        }
        *(float2*)(st + g * 64       + nt * 8 + 2 * tg) =
            make_float2(fmaxf(d0, 0.f), fmaxf(d1, 0.f));
        *(float2*)(st + (g + 8) * 64 + nt * 8 + 2 * tg) =
            make_float2(fmaxf(d2, 0.f), fmaxf(d3, 0.f));
    }
    __syncwarp();

    unsigned ah[8][4];
#pragma unroll
    for (int kt = 0; kt < 8; kt++) {
        ah[kt][0] = tf32cvt(st[g * 64       + kt * 8 + tg]);
        ah[kt][1] = tf32cvt(st[(g + 8) * 64 + kt * 8 + tg]);
        ah[kt][2] = tf32cvt(st[g * 64       + kt * 8 + tg + 4]);
        ah[kt][3] = tf32cvt(st[(g + 8) * 64 + kt * 8 + tg + 4]);
    }

    float* pbase = g_proj + (size_t)vbase * 64;
#pragma unroll
    for (int nt = 0; nt < 8; nt++) {
        float bb0 = sb2[nt * 8 + 2 * tg], bb1 = sb2[nt * 8 + 2 * tg + 1];
        float d0 = bb0, d1 = bb1, d2 = bb0, d3 = bb1;
#pragma unroll
        for (int kt = 0; kt < 8; kt++) {
            unsigned b0 = sW2[(kt * 8 + tg) * 64     + nt * 8 + g];
            unsigned b1 = sW2[(kt * 8 + tg + 4) * 64 + nt * 8 + g];
            mma_tf32(d0, d1, d2, d3, ah[kt][0], ah[kt][1], ah[kt][2], ah[kt][3], b0, b1);
        }
        *(float2*)(pbase + (size_t)g * 64       + nt * 8 + 2 * tg) = make_float2(d0, d1);
        *(float2*)(pbase + (size_t)(g + 8) * 64 + nt * 8 + 2 * tg) = make_float2(d2, d3);
    }
}

// ---------------- K4a: point -> voxel out-row map (idempotent) --------------
__global__ __launch_bounds__(256) void k_map(
    const int* __restrict__ invp, const int* __restrict__ invo)
{
    int p = blockIdx.x * 256 + threadIdx.x;
    if (p >= NPTS) return;
    g_vout[__ldg(invp + p)] = __ldg(invo + p) + 1;
}

// ---------------- K4b: per present voxel, segment-max proj into out --------
__global__ __launch_bounds__(256) void k_pmax(float* __restrict__ out)
{
    int t = blockIdx.x * 256 + threadIdx.x;
    int v = t >> 4, q = t & 15;
    if (v >= NVOX) return;
    int o = g_vout[v];
    if (o == 0) return;
    o--;
    float4 val = __ldg((const float4*)(g_proj + (size_t)v * 64) + q);
    float* ob = out + (size_t)o * 64 + q * 4;
    amaxf(ob + 0, val.x); amaxf(ob + 1, val.y);
    amaxf(ob + 2, val.z); amaxf(ob + 3, val.w);
}

// ---------------- launch ----------------------------------------------------
// Inputs identified by ELEMENT COUNT + first-appearance order (dict order):
//   400000 x4 -> inv0..inv3 ; 800000 x2 -> inv_pts, inv_out ; 25600000 -> x
//   4096 x3 -> W_red, W_fcs, W_lin2 ; 8192 x2 -> W_att, W_lin1
//   64 x2 -> b_red, b_lin2 ; 128 x2 -> b_att, b_fcs ; 1024 -> W_fc ; 2048 -> W_out
extern "C" void kernel_launch(void* const* d_in, const int* in_sizes, int n_in,
                              void* d_out, int out_size)
{
    const float *x = 0, *Wred = 0, *bred = 0, *Watt = 0, *batt = 0;
    const float *Wfcs = 0, *bfcs = 0, *Wfc = 0, *Wout = 0, *W1 = 0, *W2 = 0, *b2 = 0;
    const int *i0 = 0, *i1 = 0, *i2 = 0, *i3 = 0, *invp = 0, *invo = 0;

    int c400k = 0, c800k = 0, c4096 = 0, c8192 = 0, c64 = 0, c128 = 0;
    for (int i = 0; i < n_in; i++) {
        int s = in_sizes[i];
        const void* p = d_in[i];
        switch (s) {
            case 400000:
                if      (c400k == 0) i0 = (const int*)p;
                else if (c400k == 1) i1 = (const int*)p;
                else if (c400k == 2) i2 = (const int*)p;
                else                 i3 = (const int*)p;
                c400k++; break;
            case 800000:
                if (c800k == 0) invp = (const int*)p; else invo = (const int*)p;
                c800k++; break;
            case 25600000: x = (const float*)p; break;
            case 4096:
                if      (c4096 == 0) Wred = (const float*)p;
                else if (c4096 == 1) Wfcs = (const float*)p;
                else                 W2   = (const float*)p;
                c4096++; break;
            case 8192:
                if (c8192 == 0) Watt = (const float*)p; else W1 = (const float*)p;
                c8192++; break;
            case 64:
                if (c64 == 0) bred = (const float*)p; else b2 = (const float*)p;
                c64++; break;
            case 128:
                if (c128 == 0) batt = (const float*)p; else bfcs = (const float*)p;
                c128++; break;
            case 1024: Wfc  = (const float*)p; break;
            case 2048: Wout = (const float*)p; break;
            default: break;   // size-1 scalars ignored
        }
    }

    float* out = (float*)d_out;

    static int smem_set = 0;
    if (!smem_set) {
        cudaFuncSetAttribute(k_redmma, cudaFuncAttributeMaxDynamicSharedMemorySize,
                             REDMMA_SMEM_BYTES);
        smem_set = 1;
    }

    k_fill_out<<<(out_size + 255) / 256, 256>>>(out, out_size);

    k_wc<<<8, 256>>>(Wout, W1);

    k_map<<<(NPTS + 255) / 256, 256>>>(invp, invo);

    k_redmma<<<NVOX / 64, 128, REDMMA_SMEM_BYTES>>>(
        x, Wred, bred, W1, i0, i1, i2, i3);

    {
        long long tot = (long long)4 * NVOX * 4;
        k_scale<<<(unsigned)((tot + 255) / 256), 256>>>(Watt, batt);
    }

    k_fuse2<<<(NVOX + 255) / 256, 256>>>(Wfc, Wfcs, bfcs, i0, i1, i2, i3);

    k_out<<<NVOX / 64, 128>>>(W2, b2);   // 400000 = 64 * 6250 exactly

    k_pmax<<<((size_t)NVOX * 16 + 255) / 256, 256>>>(out);
}